// round 1
// baseline (speedup 1.0000x reference)
#include <cuda_runtime.h>
#include <cuda_bf16.h>
#include <cstdint>

// Clipped Poisson-binomial severity kernel.
// B rows, 96 probabilities per row (x1|x2|x3, 32 each).
// Recurrence over 6-vector c (absorbing top bucket), output 5 floats/row:
//   sev = [c0, c1+c2, c3+c4, c5, 0]
//
// Strategy: stage 64x32 fp32 tiles of all three inputs into shared memory with
// coalesced cp.async (padded stride-36 rows -> conflict-free LDS.128), run the
// per-row recurrence out of smem, stage outputs in smem for coalesced stores.

#define ROWS_PER_BLOCK 64
#define NTHREADS 64
#define SSTRIDE 36  // floats per padded smem row (36*4=144B, 16B aligned, bank-safe)

__global__ __launch_bounds__(NTHREADS)
void hemorrhage_sev_kernel(const float* __restrict__ x1,
                           const float* __restrict__ x2,
                           const float* __restrict__ x3,
                           float* __restrict__ out,
                           int nrows)
{
    __shared__ float s[3 * ROWS_PER_BLOCK * SSTRIDE];  // 27,648 B

    const int t = threadIdx.x;
    const long long rowBase = (long long)blockIdx.x * ROWS_PER_BLOCK;
    const int rowsHere = (int)min((long long)ROWS_PER_BLOCK, (long long)nrows - rowBase);

    const float* xs0 = x1 + rowBase * 32;
    const float* xs1 = x2 + rowBase * 32;
    const float* xs2 = x3 + rowBase * 32;
    const float* xs[3] = { xs0, xs1, xs2 };

    // ---- Stage: coalesced cp.async of 3 x (64 rows x 32 cols) fp32 ----
    // float4 granularity: 64*8 = 512 float4 per input; 8 iters x 64 threads.
    #pragma unroll
    for (int in = 0; in < 3; ++in) {
        const float4* gp = (const float4*)xs[in];
        #pragma unroll
        for (int k = 0; k < 8; ++k) {
            int i = k * NTHREADS + t;      // 0..511 float4 index in tile
            int row  = i >> 3;             // 8 float4 per row
            int col4 = i & 7;
            float* dst = &s[in * ROWS_PER_BLOCK * SSTRIDE + row * SSTRIDE + col4 * 4];
            unsigned saddr = (unsigned)__cvta_generic_to_shared(dst);
            if (row < rowsHere) {
                const float4* src = gp + i;
                asm volatile("cp.async.cg.shared.global [%0], [%1], 16;\n"
                             :: "r"(saddr), "l"(src));
            } else {
                // fill with zeros so the recurrence stays finite (result unused)
                dst[0] = 0.f; dst[1] = 0.f; dst[2] = 0.f; dst[3] = 0.f;
            }
        }
    }
    asm volatile("cp.async.commit_group;\n");
    asm volatile("cp.async.wait_group 0;\n");
    __syncthreads();

    // ---- Per-row recurrence (thread t owns local row t) ----
    float c0 = 1.f, c1 = 0.f, c2 = 0.f, c3 = 0.f, c4 = 0.f, c5 = 0.f;
    #pragma unroll
    for (int in = 0; in < 3; ++in) {
        const float* rowp = &s[in * ROWS_PER_BLOCK * SSTRIDE + t * SSTRIDE];
        #pragma unroll
        for (int j4 = 0; j4 < 8; ++j4) {
            float4 v = *(const float4*)(rowp + j4 * 4);
            float pv[4] = { v.x, v.y, v.z, v.w };
            #pragma unroll
            for (int u = 0; u < 4; ++u) {
                float p = pv[u];
                // order matters: each update reads pre-step values
                c5 = fmaf(c4, p, c5);          // absorbing top: c5 += c4*p
                c4 = fmaf(c3 - c4, p, c4);
                c3 = fmaf(c2 - c3, p, c3);
                c2 = fmaf(c1 - c2, p, c2);
                c1 = fmaf(c0 - c1, p, c1);
                c0 = fmaf(-c0, p, c0);         // c0 *= (1-p)
            }
        }
    }
    __syncthreads();  // done reading input tiles; smem will be reused for output

    // ---- Stage output: 5 floats/row, then coalesced store ----
    // stride-5 scalar STS: bank = (5t+k) mod 32, gcd(5,32)=1 -> conflict-free
    s[t * 5 + 0] = c0;
    s[t * 5 + 1] = c1 + c2;
    s[t * 5 + 2] = c3 + c4;
    s[t * 5 + 3] = c5;
    s[t * 5 + 4] = 0.f;
    __syncthreads();

    float* og = out + rowBase * 5;
    const int nOut = rowsHere * 5;
    #pragma unroll
    for (int k = 0; k < 5; ++k) {
        int idx = k * NTHREADS + t;
        if (idx < nOut) og[idx] = s[idx];
    }
}

extern "C" void kernel_launch(void* const* d_in, const int* in_sizes, int n_in,
                              void* d_out, int out_size)
{
    const float* x1 = (const float*)d_in[0];
    const float* x2 = (const float*)d_in[1];
    const float* x3 = (const float*)d_in[2];
    float* out = (float*)d_out;

    const int nrows = in_sizes[0] / 32;
    const int nblocks = (nrows + ROWS_PER_BLOCK - 1) / ROWS_PER_BLOCK;

    hemorrhage_sev_kernel<<<nblocks, NTHREADS>>>(x1, x2, x3, out, nrows);
}